// round 3
// baseline (speedup 1.0000x reference)
#include <cuda_runtime.h>
#include <math.h>

typedef unsigned long long ull;

#define BATCH 16
#define IMH 768
#define IMW 768
#define TILE 32
#define R3 9
#define LOAD 50              // TILE + 18
#define XSTR 51              // odd element stride for pair/scalar raw tiles
#define H3STR 33
#define H1ROWS 38
#define NBINS 1024
#define NTHREADS 256
#define NACC 15
#define GRID_BLOCKS ((IMW/TILE)*(IMH/TILE)*BATCH)   // 9216

// dynamic smem layout:
//  s_xy  : ull  [LOAD*XSTR]    (2550*8 = 20400 B)  pairs (x_i, y_pred)
//  s_h3xy: ull  [LOAD*H3STR]   (1650*8 = 13200 B)  pairs h-blurred G3
//  s_h3m : float[LOAD*H3STR]   (1650*4 =  6600 B)  h-blurred G3 of u
//  s_um  : float[LOAD*XSTR]    (2550*4 = 10200 B)  u raw; aliased as h1 pairs (38*33 ull = 10032 B)
//  s_hist: uint [2*NBINS]      (          8192 B)
#define SMEM_BYTES (LOAD*XSTR*8 + LOAD*H3STR*8 + LOAD*H3STR*4 + LOAD*XSTR*4 + 2*NBINS*4)

__device__ constexpr float G3W[19] = {
    0.00147944f, 0.00380430f, 0.00875341f, 0.01802349f, 0.03320783f,
    0.05475024f, 0.08077522f, 0.10663890f, 0.12597909f, 0.13317587f,
    0.12597909f, 0.10663890f, 0.08077522f, 0.05475024f, 0.03320783f,
    0.01802349f, 0.00875341f, 0.00380430f, 0.00147944f };
__device__ constexpr float G1W[7] = {
    0.00443305f, 0.05400558f, 0.24203623f, 0.39905027f,
    0.24203623f, 0.05400558f, 0.00443305f };

__device__ double       g_acc[NACC];      // zero-init at load; reset by last block
__device__ unsigned int g_hist[2*NBINS];
__device__ unsigned int g_ticket;

// ---- f32x2 packed helpers ----
__device__ __forceinline__ ull wb(float w) {           // broadcast weight to both lanes
    unsigned u = __float_as_uint(w);
    return ((ull)u << 32) | u;
}
__device__ __forceinline__ ull pk2(float lo, float hi) {
    ull r; asm("mov.b64 %0,{%1,%2};" : "=l"(r) : "f"(lo), "f"(hi)); return r;
}
__device__ __forceinline__ void up2(ull v, float& lo, float& hi) {
    asm("mov.b64 {%0,%1},%2;" : "=f"(lo), "=f"(hi) : "l"(v));
}
__device__ __forceinline__ ull fma2(ull a, ull b, ull c) {
    ull d; asm("fma.rn.f32x2 %0,%1,%2,%3;" : "=l"(d) : "l"(a), "l"(b), "l"(c)); return d;
}
__device__ __forceinline__ ull add2(ull a, ull b) {
    ull d; asm("add.rn.f32x2 %0,%1,%2;" : "=l"(d) : "l"(a), "l"(b)); return d;
}
__device__ __forceinline__ ull sub2(ull a, ull b) {
    ull d; asm("sub.rn.f32x2 %0,%1,%2;" : "=l"(d) : "l"(a), "l"(b)); return d;
}

__global__ __launch_bounds__(NTHREADS, 3)
void main_kernel(const float* __restrict__ yp_g,
                 const float* __restrict__ np_g,
                 const float* __restrict__ xi_g,
                 const float* __restrict__ xm_g,
                 const float* __restrict__ wt_g,
                 const float* __restrict__ ns_g,
                 float* __restrict__ out)
{
    extern __shared__ char smem_raw[];
    ull*   s_xy   = (ull*)smem_raw;
    ull*   s_h3xy = s_xy + LOAD*XSTR;
    float* s_h3m  = (float*)(s_h3xy + LOAD*H3STR);
    float* s_um   = s_h3m + LOAD*H3STR;
    unsigned int* s_hist = (unsigned int*)(s_um + LOAD*XSTR);
    ull*   s_h1   = (ull*)s_um;          // alias after G3 h-pass consumes u

    __shared__ float s_part[NACC][8];
    __shared__ unsigned int s_wtot[8];
    __shared__ double s_q[4];
    __shared__ bool s_last;

    const int tid = threadIdx.x;
    for (int i = tid; i < 2*NBINS; i += NTHREADS) s_hist[i] = 0u;

    const int oy = blockIdx.y * TILE;
    const int ox = blockIdx.x * TILE;
    const int img = blockIdx.z * (IMH * IMW);

    // ---- load raw tiles with halo; build pair (xi,yp) and u = yp-0.3xi-0.7xm ----
    for (int i = tid; i < LOAD*LOAD; i += NTHREADS) {
        int r = i / LOAD, c = i - r * LOAD;
        int gy = oy + r - R3, gx = ox + c - R3;
        bool in = ((unsigned)gy < IMH) & ((unsigned)gx < IMW);
        float vx = 0.f, vy = 0.f, vm = 0.f;
        if (in) {
            int g = img + gy * IMW + gx;
            vx = xi_g[g]; vy = yp_g[g]; vm = xm_g[g];
        }
        int o = r*XSTR + c;
        s_xy[o] = pk2(vx, vy);
        s_um[o] = fmaf(-0.7f, vm, fmaf(-0.3f, vx, vy));
    }
    __syncthreads();

    // ---- G3 horizontal: 50 rows x 8 groups of 4 outputs (sliding window) ----
    for (int i = tid; i < LOAD*8; i += NTHREADS) {
        int r = i >> 3, c4 = (i & 7) << 2;
        int base = r*XSTR + c4;
        ull a0=0,a1=0,a2=0,a3=0;
        float m0=0,m1=0,m2=0,m3=0;
        #pragma unroll
        for (int t = 0; t < 22; t++) {
            ull v = s_xy[base+t];
            float vu = s_um[base+t];
            if (t <= 18)           { ull w=wb(G3W[t  ]); a0=fma2(v,w,a0); m0=fmaf(vu,G3W[t  ],m0); }
            if (t >= 1 && t <= 19) { ull w=wb(G3W[t-1]); a1=fma2(v,w,a1); m1=fmaf(vu,G3W[t-1],m1); }
            if (t >= 2 && t <= 20) { ull w=wb(G3W[t-2]); a2=fma2(v,w,a2); m2=fmaf(vu,G3W[t-2],m2); }
            if (t >= 3)            { ull w=wb(G3W[t-3]); a3=fma2(v,w,a3); m3=fmaf(vu,G3W[t-3],m3); }
        }
        int o = r*H3STR + c4;
        s_h3xy[o]=a0; s_h3xy[o+1]=a1; s_h3xy[o+2]=a2; s_h3xy[o+3]=a3;
        s_h3m[o]=m0;  s_h3m[o+1]=m1;  s_h3m[o+2]=m2;  s_h3m[o+3]=m3;
    }
    __syncthreads();

    // ---- G1 horizontal into aliased s_um region (u raw no longer needed) ----
    for (int i = tid; i < H1ROWS*8; i += NTHREADS) {
        int r = i >> 3, c4 = (i & 7) << 2;
        int base = (r + 6)*XSTR + c4 + 6;
        ull a0=0,a1=0,a2=0,a3=0;
        #pragma unroll
        for (int t = 0; t < 10; t++) {
            ull v = s_xy[base+t];
            if (t <= 6)           { a0 = fma2(v, wb(G1W[t  ]), a0); }
            if (t >= 1 && t <= 7) { a1 = fma2(v, wb(G1W[t-1]), a1); }
            if (t >= 2 && t <= 8) { a2 = fma2(v, wb(G1W[t-2]), a2); }
            if (t >= 3)           { a3 = fma2(v, wb(G1W[t-3]), a3); }
        }
        int o = r*H3STR + c4;
        s_h1[o]=a0; s_h1[o+1]=a1; s_h1[o+2]=a2; s_h1[o+3]=a3;
    }
    __syncthreads();

    // ---- per-pixel phase: thread owns column c, rows r0..r0+3 ----
    const int c  = tid & 31;
    const int r0 = (tid >> 5) << 2;

    ull   LIP[4] = {0,0,0,0};     // packed (low_i, low_p)
    float LU[4]  = {0,0,0,0};     // G3(u)
    #pragma unroll
    for (int t = 0; t < 22; t++) {
        int idx = (r0 + t)*H3STR + c;
        ull v = s_h3xy[idx];
        float vu = s_h3m[idx];
        if (t <= 18)           { LIP[0]=fma2(v,wb(G3W[t  ]),LIP[0]); LU[0]=fmaf(vu,G3W[t  ],LU[0]); }
        if (t >= 1 && t <= 19) { LIP[1]=fma2(v,wb(G3W[t-1]),LIP[1]); LU[1]=fmaf(vu,G3W[t-1],LU[1]); }
        if (t >= 2 && t <= 20) { LIP[2]=fma2(v,wb(G3W[t-2]),LIP[2]); LU[2]=fmaf(vu,G3W[t-2],LU[2]); }
        if (t >= 3)            { LIP[3]=fma2(v,wb(G3W[t-3]),LIP[3]); LU[3]=fmaf(vu,G3W[t-3],LU[3]); }
    }
    ull G1P[4] = {0,0,0,0};       // packed (g1_i, g1_p)
    #pragma unroll
    for (int t = 0; t < 10; t++) {
        ull v = s_h1[(r0 + t)*H3STR + c];
        if (t <= 6)           { G1P[0]=fma2(v,wb(G1W[t  ]),G1P[0]); }
        if (t >= 1 && t <= 7) { G1P[1]=fma2(v,wb(G1W[t-1]),G1P[1]); }
        if (t >= 2 && t <= 8) { G1P[2]=fma2(v,wb(G1W[t-2]),G1P[2]); }
        if (t >= 3)           { G1P[3]=fma2(v,wb(G1W[t-3]),G1P[3]); }
    }

    float p_rc=0,p_nb=0,p_sxi=0,p_syp=0,p_ex=0,p_ey=0,p_ntex=0,p_stex=0;
    float p_nf=0,p_nfb=0,p_lf=0,p_mid=0,p_hf=0,p_syn=0,p_ic=0;

    // rolling 3x3 window over packed raw tile
    int rb = (r0 + R3 - 1)*XSTR + (c + R3 - 1);
    ull v00=s_xy[rb],      v01=s_xy[rb+1],      v02=s_xy[rb+2];
    ull v10=s_xy[rb+XSTR], v11=s_xy[rb+XSTR+1], v12=s_xy[rb+XSTR+2];
    const ull TWO2  = wb(2.0f);
    const ull NEG42 = wb(-4.0f);

    #pragma unroll
    for (int j = 0; j < 4; j++) {
        int rbn = rb + (j+2)*XSTR;
        ull v20=s_xy[rbn], v21=s_xy[rbn+1], v22=s_xy[rbn+2];

        ull gx = fma2(sub2(v12,v10), TWO2, add2(sub2(v02,v00), sub2(v22,v20)));
        ull gy = fma2(sub2(v21,v01), TWO2, add2(sub2(v20,v00), sub2(v22,v02)));
        ull lp = fma2(v11, NEG42, add2(add2(v01,v10), add2(v12,v21)));

        float gxi,gxp, gyi,gyp, lap_i,lap_p, xi,yp;
        up2(gx, gxi, gxp);
        up2(gy, gyi, gyp);
        up2(lp, lap_i, lap_p);
        up2(v11, xi, yp);

        int g = img + (oy + r0 + j)*IMW + (ox + c);
        float wv   = wt_g[g];
        float nprd = np_g[g];
        float nsyn = ns_g[g];

        p_rc += fabsf(yp*wv - xi*wv);

        bool body = (xi > 0.15f) & (xi < 0.85f);
        if (body) {
            p_nb += 1.f; p_sxi += xi; p_syp += yp;
            int b1 = min(max((int)(yp * (float)NBINS), 0), NBINS-1);
            atomicAdd(&s_hist[b1], 1u);
            int b2 = min(max((int)(xi * (float)NBINS), 0), NBINS-1);
            atomicAdd(&s_hist[NBINS + b2], 1u);
        }

        float gmi = sqrtf(fmaf(gxi,gxi, gyi*gyi) + 1e-8f);
        float gmp = sqrtf(fmaf(gxp,gxp, gyp*gyp) + 1e-8f);

        p_ex += fabsf(gxp - gxi);
        p_ey += fabsf(gyp - gyi);

        bool tex = (gmi > 0.03f) & (gmi < 0.5f);
        if (tex) { p_ntex += 1.f; p_stex += fabsf(gmp - gmi); }

        bool flat = (gmi < 0.03f);
        if (flat) {
            p_nf += 1.f;
            p_hf += fabsf(fabsf(lap_p) - 0.3f*fabsf(lap_i));
            p_ic += fmaxf(gmp - 2.0f*gmi, 0.f);
            if (body) {
                p_nfb += 1.f;
                p_lf  += fabsf(LU[j]);
                float low_i, low_p, g1i, g1p;
                up2(LIP[j], low_i, low_p);
                up2(G1P[j], g1i, g1p);
                p_mid += fabsf(fabsf(g1p - low_p) - 0.3f*fabsf(g1i - low_i));
                p_syn += fabsf(nprd - nsyn);
            }
        }

        v00=v10; v01=v11; v02=v12; v10=v20; v11=v21; v12=v22;
    }

    // ---- block reduction of 15 partials ----
    float vals[NACC] = {p_rc, p_nb, p_sxi, p_syp, p_ex, p_ey, p_ntex, p_stex,
                        p_nf, p_nfb, p_lf, p_mid, p_hf, p_syn, p_ic};
    int lane = tid & 31, warp = tid >> 5;
    #pragma unroll
    for (int q = 0; q < NACC; q++) {
        float v = vals[q];
        #pragma unroll
        for (int o = 16; o > 0; o >>= 1) v += __shfl_down_sync(0xffffffffu, v, o);
        if (lane == 0) s_part[q][warp] = v;
    }
    __syncthreads();
    if (tid < NACC) {
        float s = 0.f;
        #pragma unroll
        for (int w = 0; w < 8; w++) s += s_part[tid][w];
        atomicAdd(&g_acc[tid], (double)s);
    }
    for (int i = tid; i < 2*NBINS; i += NTHREADS) {
        unsigned int h = s_hist[i];
        if (h) atomicAdd(&g_hist[i], h);
    }

    // ---- last-block finalize (ticket pattern) ----
    __syncthreads();
    if (tid == 0) {
        __threadfence();
        unsigned t = atomicAdd(&g_ticket, 1u);
        s_last = (t == GRID_BLOCKS - 1);
    }
    __syncthreads();
    if (!s_last) return;
    __threadfence();

    unsigned int* s_cum = s_hist;   // reuse dyn smem (2048 uints available)
    const double nb = g_acc[1];

    for (int h = 0; h < 2; h++) {
        unsigned int loc[4];
        unsigned int run = 0;
        #pragma unroll
        for (int k = 0; k < 4; k++) { run += g_hist[h*NBINS + tid*4 + k]; loc[k] = run; }
        unsigned int v = run;
        #pragma unroll
        for (int o = 1; o < 32; o <<= 1) {
            unsigned int u = __shfl_up_sync(0xffffffffu, v, o);
            if (lane >= o) v += u;
        }
        __syncthreads();           // protect s_wtot across h iterations
        if (lane == 31) s_wtot[warp] = v;
        __syncthreads();
        unsigned int woff = 0;
        for (int w = 0; w < warp; w++) woff += s_wtot[w];
        unsigned int off = woff + v - run;
        #pragma unroll
        for (int k = 0; k < 4; k++) s_cum[tid*4 + k] = loc[k] + off;
        __syncthreads();
        if (tid < 2) {
            double q = (tid == 0) ? 0.25 : 0.75;
            double pos = q * (nb - 1.0);
            int lo = 0, hi = NBINS - 1;
            while (lo < hi) {
                int m = (lo + hi) >> 1;
                if ((double)s_cum[m] > pos) hi = m; else lo = m + 1;
            }
            int b = lo;
            unsigned int cb = s_cum[b];
            unsigned int pv = b ? s_cum[b-1] : 0u;
            double cnt = (double)(cb - pv);
            double val = 0.0;
            if (cnt > 0.0) {
                double frac = (pos - (double)pv + 0.5) / cnt;
                frac = fmin(fmax(frac, 0.0), 1.0);
                val = ((double)b + frac) / (double)NBINS;
            }
            s_q[h*2 + tid] = val;
        }
        __syncthreads();
    }

    if (tid == 0) {
        const double n_all = (double)BATCH * IMH * IMW;
        double rc = g_acc[0] / n_all;
        double denb = fmax(nb, 1.0);
        double mean_in = g_acc[2] / denb;
        double mean_pr = g_acc[3] / denb;
        double dm  = mean_pr - mean_in;
        double d25 = s_q[0] - s_q[2];
        double d75 = s_q[1] - s_q[3];
        double hu  = dm*dm + 0.5*(d25*d25 + d75*d75);
        double loss_hu = (nb > 4096.0) ? hu : 0.0;
        double edge = g_acc[4]/n_all + g_acc[5]/n_all;
        double ntex = g_acc[6];
        double tex = (ntex > 100.0) ? g_acc[7]/fmax(ntex, 1.0) : 0.0;
        double nf = g_acc[8], nfb = g_acc[9];
        double lf  = (nfb > 100.0) ? g_acc[10]/fmax(nfb, 1.0) : 0.0;
        double mid = (nfb > 100.0) ? g_acc[11]/fmax(nfb, 1.0) : 0.0;
        double hf  = (nf  > 100.0) ? g_acc[12]/fmax(nf, 1.0)  : 0.0;
        double syn = (nfb > 100.0) ? g_acc[13]/fmax(nfb, 1.0) : 0.0;
        double ic  = (nf  > 100.0) ? g_acc[14]/fmax(nf, 1.0)  : 0.0;

        double total = 2.0*rc + 1.5*loss_hu + 1.0*edge + 0.8*tex
                     + 1.5*hf + 0.8*mid + 0.6*lf + 1.0*syn + 0.8*ic;
        out[0] = (float)total;
    }
    __syncthreads();

    // reset global state for next invocation
    for (int i = tid; i < 2*NBINS; i += NTHREADS) g_hist[i] = 0u;
    if (tid < NACC) g_acc[tid] = 0.0;
    if (tid == 0) g_ticket = 0u;
}

extern "C" void kernel_launch(void* const* d_in, const int* in_sizes, int n_in,
                              void* d_out, int out_size) {
    const float* yp = (const float*)d_in[0];   // y_pred
    const float* np = (const float*)d_in[1];   // noise_pred
    const float* xi = (const float*)d_in[2];   // x_i
    // d_in[3] = x_ip1 (unused by reference)
    const float* xm = (const float*)d_in[4];   // x_mid
    const float* wt = (const float*)d_in[5];   // W
    const float* ns = (const float*)d_in[6];   // noise_synthetic
    float* out = (float*)d_out;

    cudaFuncSetAttribute(main_kernel,
                         cudaFuncAttributeMaxDynamicSharedMemorySize, SMEM_BYTES);

    dim3 grid(IMW / TILE, IMH / TILE, BATCH);
    main_kernel<<<grid, NTHREADS, SMEM_BYTES>>>(yp, np, xi, xm, wt, ns, out);
}

// round 5
// speedup vs baseline: 1.3156x; 1.3156x over previous
#include <cuda_runtime.h>
#include <math.h>

#define BATCH 16
#define IMH 768
#define IMW 768
#define TILE 32
#define R3 9
#define LOAD 50              // TILE + 18
#define RSTR 53              // odd stride -> conflict-free
#define H3STR 33
#define H1ROWS 38
#define NBINS 512
#define NWORDS (NBINS/2)     // two u16 bins per u32 word
#define NTHREADS 256
#define NACC 15
#define GRID_BLOCKS ((IMW/TILE)*(IMH/TILE)*BATCH)   // 9216
#define P3 (LOAD*H3STR)
#define P1 (H1ROWS*H3STR)

// dynamic smem (floats unless noted):
//  s_xi : LOAD*RSTR (2650)   s_yp : LOAD*RSTR   s_um : LOAD*RSTR (aliased as h1 after G3-h)
//  s_h3 : 3*LOAD*H3STR (4950)
//  s_hist: 2*NWORDS u32 (512 words = 2KB)
#define SMEM_FLOATS (3*LOAD*RSTR + 3*LOAD*H3STR)
#define SMEM_BYTES  (SMEM_FLOATS*4 + 2*NWORDS*4)

__device__ constexpr float G3W[19] = {
    0.00147944f, 0.00380430f, 0.00875341f, 0.01802349f, 0.03320783f,
    0.05475024f, 0.08077522f, 0.10663890f, 0.12597909f, 0.13317587f,
    0.12597909f, 0.10663890f, 0.08077522f, 0.05475024f, 0.03320783f,
    0.01802349f, 0.00875341f, 0.00380430f, 0.00147944f };
__device__ constexpr float G1W[7] = {
    0.00443305f, 0.05400558f, 0.24203623f, 0.39905027f,
    0.24203623f, 0.05400558f, 0.00443305f };

__device__ double       g_acc[NACC];          // zero-init at load; reset by last block
__device__ unsigned int g_histp[2*NWORDS];    // packed u16 pairs
__device__ unsigned int g_ticket;

__global__ __launch_bounds__(NTHREADS, 4)
void main_kernel(const float* __restrict__ yp_g,
                 const float* __restrict__ np_g,
                 const float* __restrict__ xi_g,
                 const float* __restrict__ xm_g,
                 const float* __restrict__ wt_g,
                 const float* __restrict__ ns_g,
                 float* __restrict__ out)
{
    extern __shared__ float smem[];
    float* s_xi = smem;
    float* s_yp = s_xi + LOAD*RSTR;
    float* s_um = s_yp + LOAD*RSTR;      // u raw; aliased as h1 planes after G3 h-pass
    float* s_h3 = s_um + LOAD*RSTR;      // 3 planes (xi, yp, u)
    unsigned int* s_hist = (unsigned int*)(s_h3 + 3*P3);  // 2*NWORDS
    float* s_h1 = s_um;                  // 2 planes of H1ROWS*H3STR (10032B <= 10600B)

    __shared__ float s_part[NACC][8];
    __shared__ unsigned int s_wtot[8];
    __shared__ double s_q[4];
    __shared__ bool s_last;

    const int tid = threadIdx.x;
    for (int i = tid; i < 2*NWORDS; i += NTHREADS) s_hist[i] = 0u;

    const int oy = blockIdx.y * TILE;
    const int ox = blockIdx.x * TILE;
    const int img = blockIdx.z * (IMH * IMW);

    // ---- load raw tiles with halo; u = yp - 0.3*xi - 0.7*xm ----
    for (int i = tid; i < LOAD*LOAD; i += NTHREADS) {
        int r = i / LOAD, c = i - r * LOAD;
        int gy = oy + r - R3, gx = ox + c - R3;
        bool in = ((unsigned)gy < IMH) & ((unsigned)gx < IMW);
        float vx = 0.f, vy = 0.f, vm = 0.f;
        if (in) {
            int g = img + gy * IMW + gx;
            vx = xi_g[g]; vy = yp_g[g]; vm = xm_g[g];
        }
        int o = r*RSTR + c;
        s_xi[o] = vx; s_yp[o] = vy;
        s_um[o] = fmaf(-0.7f, vm, fmaf(-0.3f, vx, vy));
    }
    __syncthreads();

    // ---- G3 horizontal: 50 rows x 8 groups of 4 outputs, sliding window ----
    for (int i = tid; i < LOAD*8; i += NTHREADS) {
        int r = i >> 3, c4 = (i & 7) << 2;
        int base = r*RSTR + c4;
        float a0=0,a1=0,a2=0,a3=0, b0=0,b1=0,b2=0,b3=0, m0=0,m1=0,m2=0,m3=0;
        #pragma unroll
        for (int t = 0; t < 22; t++) {
            float vx = s_xi[base+t], vy = s_yp[base+t], vm = s_um[base+t];
            if (t <= 18)           { a0+=G3W[t  ]*vx; b0+=G3W[t  ]*vy; m0+=G3W[t  ]*vm; }
            if (t >= 1 && t <= 19) { a1+=G3W[t-1]*vx; b1+=G3W[t-1]*vy; m1+=G3W[t-1]*vm; }
            if (t >= 2 && t <= 20) { a2+=G3W[t-2]*vx; b2+=G3W[t-2]*vy; m2+=G3W[t-2]*vm; }
            if (t >= 3)            { a3+=G3W[t-3]*vx; b3+=G3W[t-3]*vy; m3+=G3W[t-3]*vm; }
        }
        int o = r*H3STR + c4;
        s_h3[o]=a0; s_h3[o+1]=a1; s_h3[o+2]=a2; s_h3[o+3]=a3;
        s_h3[P3+o]=b0; s_h3[P3+o+1]=b1; s_h3[P3+o+2]=b2; s_h3[P3+o+3]=b3;
        s_h3[2*P3+o]=m0; s_h3[2*P3+o+1]=m1; s_h3[2*P3+o+2]=m2; s_h3[2*P3+o+3]=m3;
    }
    __syncthreads();

    // ---- G1 horizontal into aliased s_um (u raw fully consumed) ----
    for (int i = tid; i < H1ROWS*8; i += NTHREADS) {
        int r = i >> 3, c4 = (i & 7) << 2;
        int base = (r + 6)*RSTR + c4 + 6;
        float a0=0,a1=0,a2=0,a3=0, b0=0,b1=0,b2=0,b3=0;
        #pragma unroll
        for (int t = 0; t < 10; t++) {
            float vx = s_xi[base+t], vy = s_yp[base+t];
            if (t <= 6)           { a0+=G1W[t  ]*vx; b0+=G1W[t  ]*vy; }
            if (t >= 1 && t <= 7) { a1+=G1W[t-1]*vx; b1+=G1W[t-1]*vy; }
            if (t >= 2 && t <= 8) { a2+=G1W[t-2]*vx; b2+=G1W[t-2]*vy; }
            if (t >= 3)           { a3+=G1W[t-3]*vx; b3+=G1W[t-3]*vy; }
        }
        int o = r*H3STR + c4;
        s_h1[o]=a0; s_h1[o+1]=a1; s_h1[o+2]=a2; s_h1[o+3]=a3;
        s_h1[P1+o]=b0; s_h1[P1+o+1]=b1; s_h1[P1+o+2]=b2; s_h1[P1+o+3]=b3;
    }
    __syncthreads();

    // ---- per-pixel phase: thread owns column c, rows r0..r0+3 ----
    const int c  = tid & 31;
    const int r0 = (tid >> 5) << 2;

    float LI[4]={0,0,0,0}, LP[4]={0,0,0,0}, LU[4]={0,0,0,0};
    #pragma unroll
    for (int t = 0; t < 22; t++) {
        int idx = (r0 + t)*H3STR + c;
        float vx = s_h3[idx], vy = s_h3[P3+idx], vu = s_h3[2*P3+idx];
        if (t <= 18)           { LI[0]+=G3W[t  ]*vx; LP[0]+=G3W[t  ]*vy; LU[0]+=G3W[t  ]*vu; }
        if (t >= 1 && t <= 19) { LI[1]+=G3W[t-1]*vx; LP[1]+=G3W[t-1]*vy; LU[1]+=G3W[t-1]*vu; }
        if (t >= 2 && t <= 20) { LI[2]+=G3W[t-2]*vx; LP[2]+=G3W[t-2]*vy; LU[2]+=G3W[t-2]*vu; }
        if (t >= 3)            { LI[3]+=G3W[t-3]*vx; LP[3]+=G3W[t-3]*vy; LU[3]+=G3W[t-3]*vu; }
    }
    float GI[4]={0,0,0,0}, GP[4]={0,0,0,0};
    #pragma unroll
    for (int t = 0; t < 10; t++) {
        int idx = (r0 + t)*H3STR + c;
        float vx = s_h1[idx], vy = s_h1[P1+idx];
        if (t <= 6)           { GI[0]+=G1W[t  ]*vx; GP[0]+=G1W[t  ]*vy; }
        if (t >= 1 && t <= 7) { GI[1]+=G1W[t-1]*vx; GP[1]+=G1W[t-1]*vy; }
        if (t >= 2 && t <= 8) { GI[2]+=G1W[t-2]*vx; GP[2]+=G1W[t-2]*vy; }
        if (t >= 3)           { GI[3]+=G1W[t-3]*vx; GP[3]+=G1W[t-3]*vy; }
    }

    float p_rc=0,p_nb=0,p_sxi=0,p_syp=0,p_ex=0,p_ey=0,p_ntex=0,p_stex=0;
    float p_nf=0,p_nfb=0,p_lf=0,p_mid=0,p_hf=0,p_syn=0,p_ic=0;

    int rb = (r0 + R3 - 1)*RSTR + (c + R3 - 1);
    float x00=s_xi[rb],      x01=s_xi[rb+1],      x02=s_xi[rb+2];
    float y00=s_yp[rb],      y01=s_yp[rb+1],      y02=s_yp[rb+2];
    float x10=s_xi[rb+RSTR], x11=s_xi[rb+RSTR+1], x12=s_xi[rb+RSTR+2];
    float y10=s_yp[rb+RSTR], y11=s_yp[rb+RSTR+1], y12=s_yp[rb+RSTR+2];

    #pragma unroll
    for (int j = 0; j < 4; j++) {
        int rbn = rb + (j+2)*RSTR;
        float x20=s_xi[rbn], x21=s_xi[rbn+1], x22=s_xi[rbn+2];
        float y20=s_yp[rbn], y21=s_yp[rbn+1], y22=s_yp[rbn+2];

        float gxi = (x02 - x00) + 2.f*(x12 - x10) + (x22 - x20);
        float gyi = (x20 - x00) + 2.f*(x21 - x01) + (x22 - x02);
        float lap_i = x01 + x10 + x12 + x21 - 4.f*x11;
        float gxp = (y02 - y00) + 2.f*(y12 - y10) + (y22 - y20);
        float gyp = (y20 - y00) + 2.f*(y21 - y01) + (y22 - y02);
        float lap_p = y01 + y10 + y12 + y21 - 4.f*y11;

        float xi = x11, yp = y11;

        int g = img + (oy + r0 + j)*IMW + (ox + c);
        float wv   = wt_g[g];
        float nprd = np_g[g];
        float nsyn = ns_g[g];

        p_rc += fabsf(yp*wv - xi*wv);

        bool body = (xi > 0.15f) & (xi < 0.85f);
        if (body) {
            p_nb += 1.f; p_sxi += xi; p_syp += yp;
            int b1 = min(max((int)(yp * (float)NBINS), 0), NBINS-1);
            atomicAdd(&s_hist[b1 >> 1], 1u << ((b1 & 1) * 16));
            int b2 = min(max((int)(xi * (float)NBINS), 0), NBINS-1);
            atomicAdd(&s_hist[NWORDS + (b2 >> 1)], 1u << ((b2 & 1) * 16));
        }

        float gmi = sqrtf(fmaf(gxi,gxi, gyi*gyi) + 1e-8f);
        float gmp = sqrtf(fmaf(gxp,gxp, gyp*gyp) + 1e-8f);

        p_ex += fabsf(gxp - gxi);
        p_ey += fabsf(gyp - gyi);

        bool tex = (gmi > 0.03f) & (gmi < 0.5f);
        if (tex) { p_ntex += 1.f; p_stex += fabsf(gmp - gmi); }

        bool flat = (gmi < 0.03f);
        if (flat) {
            p_nf += 1.f;
            p_hf += fabsf(fabsf(lap_p) - 0.3f*fabsf(lap_i));
            p_ic += fmaxf(gmp - 2.0f*gmi, 0.f);
            if (body) {
                p_nfb += 1.f;
                p_lf  += fabsf(LU[j]);
                p_mid += fabsf(fabsf(GP[j] - LP[j]) - 0.3f*fabsf(GI[j] - LI[j]));
                p_syn += fabsf(nprd - nsyn);
            }
        }

        x00=x10; x01=x11; x02=x12; x10=x20; x11=x21; x12=x22;
        y00=y10; y01=y11; y02=y12; y10=y20; y11=y21; y12=y22;
    }

    // ---- block reduction of 15 partials ----
    float vals[NACC] = {p_rc, p_nb, p_sxi, p_syp, p_ex, p_ey, p_ntex, p_stex,
                        p_nf, p_nfb, p_lf, p_mid, p_hf, p_syn, p_ic};
    int lane = tid & 31, warp = tid >> 5;
    #pragma unroll
    for (int q = 0; q < NACC; q++) {
        float v = vals[q];
        #pragma unroll
        for (int o = 16; o > 0; o >>= 1) v += __shfl_down_sync(0xffffffffu, v, o);
        if (lane == 0) s_part[q][warp] = v;
    }
    __syncthreads();
    if (tid < NACC) {
        float s = 0.f;
        #pragma unroll
        for (int w = 0; w < 8; w++) s += s_part[tid][w];
        atomicAdd(&g_acc[tid], (double)s);
    }
    for (int i = tid; i < 2*NWORDS; i += NTHREADS) {
        unsigned int h = s_hist[i];
        if (h) atomicAdd(&g_histp[i], h);
    }

    // ---- last-block finalize ----
    __syncthreads();
    if (tid == 0) {
        __threadfence();
        unsigned t = atomicAdd(&g_ticket, 1u);
        s_last = (t == GRID_BLOCKS - 1);
    }
    __syncthreads();
    if (!s_last) return;
    __threadfence();

    unsigned int* s_cum = s_hist;   // 512 u32 slots, reused
    const double nb = g_acc[1];

    for (int h = 0; h < 2; h++) {
        unsigned int w0 = g_histp[h*NWORDS + tid];  // bins 2*tid, 2*tid+1
        unsigned int lo = w0 & 0xffffu, hi = w0 >> 16;
        unsigned int run = lo + hi;
        unsigned int v = run;
        #pragma unroll
        for (int o = 1; o < 32; o <<= 1) {
            unsigned int u = __shfl_up_sync(0xffffffffu, v, o);
            if (lane >= o) v += u;
        }
        __syncthreads();
        if (lane == 31) s_wtot[warp] = v;
        __syncthreads();
        unsigned int woff = 0;
        for (int w = 0; w < warp; w++) woff += s_wtot[w];
        unsigned int off = woff + v - run;
        s_cum[2*tid]   = off + lo;
        s_cum[2*tid+1] = off + run;
        __syncthreads();
        if (tid < 2) {
            double q = (tid == 0) ? 0.25 : 0.75;
            double pos = q * (nb - 1.0);
            int lo_i = 0, hi_i = NBINS - 1;
            while (lo_i < hi_i) {
                int m = (lo_i + hi_i) >> 1;
                if ((double)s_cum[m] > pos) hi_i = m; else lo_i = m + 1;
            }
            int b = lo_i;
            unsigned int cb = s_cum[b];
            unsigned int pv = b ? s_cum[b-1] : 0u;
            double cnt = (double)(cb - pv);
            double val = 0.0;
            if (cnt > 0.0) {
                double frac = (pos - (double)pv + 0.5) / cnt;
                frac = fmin(fmax(frac, 0.0), 1.0);
                val = ((double)b + frac) / (double)NBINS;
            }
            s_q[h*2 + tid] = val;
        }
        __syncthreads();
    }

    if (tid == 0) {
        const double n_all = (double)BATCH * IMH * IMW;
        double rc = g_acc[0] / n_all;
        double denb = fmax(nb, 1.0);
        double mean_in = g_acc[2] / denb;
        double mean_pr = g_acc[3] / denb;
        double dm  = mean_pr - mean_in;
        double d25 = s_q[0] - s_q[2];
        double d75 = s_q[1] - s_q[3];
        double hu  = dm*dm + 0.5*(d25*d25 + d75*d75);
        double loss_hu = (nb > 4096.0) ? hu : 0.0;
        double edge = g_acc[4]/n_all + g_acc[5]/n_all;
        double ntex = g_acc[6];
        double tex = (ntex > 100.0) ? g_acc[7]/fmax(ntex, 1.0) : 0.0;
        double nf = g_acc[8], nfb = g_acc[9];
        double lf  = (nfb > 100.0) ? g_acc[10]/fmax(nfb, 1.0) : 0.0;
        double mid = (nfb > 100.0) ? g_acc[11]/fmax(nfb, 1.0) : 0.0;
        double hf  = (nf  > 100.0) ? g_acc[12]/fmax(nf, 1.0)  : 0.0;
        double syn = (nfb > 100.0) ? g_acc[13]/fmax(nfb, 1.0) : 0.0;
        double ic  = (nf  > 100.0) ? g_acc[14]/fmax(nf, 1.0)  : 0.0;

        double total = 2.0*rc + 1.5*loss_hu + 1.0*edge + 0.8*tex
                     + 1.5*hf + 0.8*mid + 0.6*lf + 1.0*syn + 0.8*ic;
        out[0] = (float)total;
    }
    __syncthreads();

    for (int i = tid; i < 2*NWORDS; i += NTHREADS) g_histp[i] = 0u;
    if (tid < NACC) g_acc[tid] = 0.0;
    if (tid == 0) g_ticket = 0u;
}

extern "C" void kernel_launch(void* const* d_in, const int* in_sizes, int n_in,
                              void* d_out, int out_size) {
    const float* yp = (const float*)d_in[0];   // y_pred
    const float* np = (const float*)d_in[1];   // noise_pred
    const float* xi = (const float*)d_in[2];   // x_i
    // d_in[3] = x_ip1 (unused by reference)
    const float* xm = (const float*)d_in[4];   // x_mid
    const float* wt = (const float*)d_in[5];   // W
    const float* ns = (const float*)d_in[6];   // noise_synthetic
    float* out = (float*)d_out;

    cudaFuncSetAttribute(main_kernel,
                         cudaFuncAttributeMaxDynamicSharedMemorySize, SMEM_BYTES);

    dim3 grid(IMW / TILE, IMH / TILE, BATCH);
    main_kernel<<<grid, NTHREADS, SMEM_BYTES>>>(yp, np, xi, xm, wt, ns, out);
}

// round 7
// speedup vs baseline: 1.4965x; 1.1375x over previous
#include <cuda_runtime.h>
#include <cuda_fp16.h>
#include <math.h>

#define BATCH 16
#define IMH 768
#define IMW 768
#define TILE 32
#define R3 9
#define LOAD 50              // TILE + 18
#define XSTR 53              // half2 raw tile stride (elements) - odd, conflict-free
#define USTR 51              // half u tile stride
#define HSTR 33              // blurred plane stride
#define H1ROWS 38
#define NBINS 512
#define NWORDS (NBINS/2)
#define NTHREADS 256
#define NACC 15
#define GRID_BLOCKS ((IMW/TILE)*(IMH/TILE)*BATCH)   // 9216

// byte offsets in dynamic smem
#define OFF_XY   0                               // half2[50*53]  = 10600 B
#define OFF_H3   (OFF_XY + LOAD*XSTR*4)          // half2[50*33]  =  6600 B
#define OFF_H3U  (OFF_H3 + LOAD*HSTR*4)          // half [50*33]  =  3300 B
#define OFF_U    (OFF_H3U + LOAD*HSTR*2)         // half [50*51]  =  5100 B (aliased by h1: half2[38*33]=5016)
#define OFF_HIST (OFF_U + LOAD*USTR*2)           // u32 [512]     =  2048 B
#define SMEM_BYTES (OFF_HIST + 2*NWORDS*4)       // 27648 B

__device__ constexpr float G3W[19] = {
    0.00147944f, 0.00380430f, 0.00875341f, 0.01802349f, 0.03320783f,
    0.05475024f, 0.08077522f, 0.10663890f, 0.12597909f, 0.13317587f,
    0.12597909f, 0.10663890f, 0.08077522f, 0.05475024f, 0.03320783f,
    0.01802349f, 0.00875341f, 0.00380430f, 0.00147944f };
__device__ constexpr float G1W[7] = {
    0.00443305f, 0.05400558f, 0.24203623f, 0.39905027f,
    0.24203623f, 0.05400558f, 0.00443305f };

__device__ double       g_acc[NACC];
__device__ unsigned int g_histp[2*NWORDS];
__device__ unsigned int g_ticket;

__global__ __launch_bounds__(NTHREADS, 4)
void main_kernel(const float* __restrict__ yp_g,
                 const float* __restrict__ np_g,
                 const float* __restrict__ xi_g,
                 const float* __restrict__ xm_g,
                 const float* __restrict__ wt_g,
                 const float* __restrict__ ns_g,
                 float* __restrict__ out)
{
    extern __shared__ char smem_raw[];
    __half2* s_xy  = (__half2*)(smem_raw + OFF_XY);
    __half2* s_h3  = (__half2*)(smem_raw + OFF_H3);
    __half*  s_h3u = (__half*)(smem_raw + OFF_H3U);
    __half*  s_u   = (__half*)(smem_raw + OFF_U);
    __half2* s_h1  = (__half2*)(smem_raw + OFF_U);   // alias, used after G3-h
    unsigned int* s_hist = (unsigned int*)(smem_raw + OFF_HIST);

    __shared__ float s_part[NACC][8];
    __shared__ unsigned int s_wtot[8];
    __shared__ double s_q[4];
    __shared__ bool s_last;

    const int tid = threadIdx.x;
    for (int i = tid; i < 2*NWORDS; i += NTHREADS) s_hist[i] = 0u;

    // packed weights (constants; compiler keeps in regs/URs under full unroll)
    __half2 w3[19], w1[7];
    __half  w3s[19], w1s[7];
    #pragma unroll
    for (int t = 0; t < 19; t++) { w3[t] = __float2half2_rn(G3W[t]); w3s[t] = __float2half_rn(G3W[t]); }
    #pragma unroll
    for (int t = 0; t < 7; t++)  { w1[t] = __float2half2_rn(G1W[t]); w1s[t] = __float2half_rn(G1W[t]); }

    const int oy = blockIdx.y * TILE;
    const int ox = blockIdx.x * TILE;
    const int img = blockIdx.z * (IMH * IMW);

    // ---- load raw tiles: (xi,yp) packed half2, u = yp-0.3xi-0.7xm as half ----
    for (int i = tid; i < LOAD*LOAD; i += NTHREADS) {
        int r = i / LOAD, c = i - r * LOAD;
        int gy = oy + r - R3, gx = ox + c - R3;
        bool in = ((unsigned)gy < IMH) & ((unsigned)gx < IMW);
        float vx = 0.f, vy = 0.f, vm = 0.f;
        if (in) {
            int g = img + gy * IMW + gx;
            vx = xi_g[g]; vy = yp_g[g]; vm = xm_g[g];
        }
        s_xy[r*XSTR + c] = __floats2half2_rn(vx, vy);   // low=xi, high=yp
        s_u [r*USTR + c] = __float2half_rn(fmaf(-0.7f, vm, fmaf(-0.3f, vx, vy)));
    }
    __syncthreads();

    // ---- G3 horizontal: 50 rows x 8 groups of 4 outputs ----
    for (int i = tid; i < LOAD*8; i += NTHREADS) {
        int r = i >> 3, c4 = (i & 7) << 2;
        int bx = r*XSTR + c4, bu = r*USTR + c4;
        __half2 a0 = __float2half2_rn(0.f), a1 = a0, a2 = a0, a3 = a0;
        __half  m0 = __float2half_rn(0.f), m1 = m0, m2 = m0, m3 = m0;
        #pragma unroll
        for (int t = 0; t < 22; t++) {
            __half2 v = s_xy[bx + t];
            __half vu = s_u[bu + t];
            if (t <= 18)           { a0 = __hfma2(v, w3[t  ], a0); m0 = __hfma(vu, w3s[t  ], m0); }
            if (t >= 1 && t <= 19) { a1 = __hfma2(v, w3[t-1], a1); m1 = __hfma(vu, w3s[t-1], m1); }
            if (t >= 2 && t <= 20) { a2 = __hfma2(v, w3[t-2], a2); m2 = __hfma(vu, w3s[t-2], m2); }
            if (t >= 3)            { a3 = __hfma2(v, w3[t-3], a3); m3 = __hfma(vu, w3s[t-3], m3); }
        }
        int o = r*HSTR + c4;
        s_h3[o]=a0; s_h3[o+1]=a1; s_h3[o+2]=a2; s_h3[o+3]=a3;
        s_h3u[o]=m0; s_h3u[o+1]=m1; s_h3u[o+2]=m2; s_h3u[o+3]=m3;
    }
    __syncthreads();

    // ---- G1 horizontal into aliased h1 (u raw fully consumed) ----
    for (int i = tid; i < H1ROWS*8; i += NTHREADS) {
        int r = i >> 3, c4 = (i & 7) << 2;
        int bx = (r + 6)*XSTR + c4 + 6;
        __half2 a0 = __float2half2_rn(0.f), a1 = a0, a2 = a0, a3 = a0;
        #pragma unroll
        for (int t = 0; t < 10; t++) {
            __half2 v = s_xy[bx + t];
            if (t <= 6)           { a0 = __hfma2(v, w1[t  ], a0); }
            if (t >= 1 && t <= 7) { a1 = __hfma2(v, w1[t-1], a1); }
            if (t >= 2 && t <= 8) { a2 = __hfma2(v, w1[t-2], a2); }
            if (t >= 3)           { a3 = __hfma2(v, w1[t-3], a3); }
        }
        int o = r*HSTR + c4;
        s_h1[o]=a0; s_h1[o+1]=a1; s_h1[o+2]=a2; s_h1[o+3]=a3;
    }
    __syncthreads();

    // ---- per-pixel phase: thread owns column c, rows r0..r0+3 ----
    const int c  = tid & 31;
    const int r0 = (tid >> 5) << 2;

    __half2 LIP[4]; __half LU[4];
    #pragma unroll
    for (int j = 0; j < 4; j++) { LIP[j] = __float2half2_rn(0.f); LU[j] = __float2half_rn(0.f); }
    #pragma unroll
    for (int t = 0; t < 22; t++) {
        int idx = (r0 + t)*HSTR + c;
        __half2 v = s_h3[idx];
        __half vu = s_h3u[idx];
        if (t <= 18)           { LIP[0]=__hfma2(v,w3[t  ],LIP[0]); LU[0]=__hfma(vu,w3s[t  ],LU[0]); }
        if (t >= 1 && t <= 19) { LIP[1]=__hfma2(v,w3[t-1],LIP[1]); LU[1]=__hfma(vu,w3s[t-1],LU[1]); }
        if (t >= 2 && t <= 20) { LIP[2]=__hfma2(v,w3[t-2],LIP[2]); LU[2]=__hfma(vu,w3s[t-2],LU[2]); }
        if (t >= 3)            { LIP[3]=__hfma2(v,w3[t-3],LIP[3]); LU[3]=__hfma(vu,w3s[t-3],LU[3]); }
    }
    __half2 G1P[4];
    #pragma unroll
    for (int j = 0; j < 4; j++) G1P[j] = __float2half2_rn(0.f);
    #pragma unroll
    for (int t = 0; t < 10; t++) {
        __half2 v = s_h1[(r0 + t)*HSTR + c];
        if (t <= 6)           { G1P[0]=__hfma2(v,w1[t  ],G1P[0]); }
        if (t >= 1 && t <= 7) { G1P[1]=__hfma2(v,w1[t-1],G1P[1]); }
        if (t >= 2 && t <= 8) { G1P[2]=__hfma2(v,w1[t-2],G1P[2]); }
        if (t >= 3)           { G1P[3]=__hfma2(v,w1[t-3],G1P[3]); }
    }

    float p_rc=0,p_nb=0,p_sxi=0,p_syp=0,p_ntex=0,p_stex=0;
    float p_nf=0,p_nfb=0,p_syn=0,p_ic=0;
    __half pex = __float2half_rn(0.f), pey = pex, plf = pex, pmid = pex, phf = pex;
    const __half  c03 = __float2half_rn(0.3f);
    const __half2 TWO2 = __float2half2_rn(2.0f);
    const __half2 NEG42 = __float2half2_rn(-4.0f);

    int rb = (r0 + R3 - 1)*XSTR + (c + R3 - 1);
    __half2 v00=s_xy[rb],      v01=s_xy[rb+1],      v02=s_xy[rb+2];
    __half2 v10=s_xy[rb+XSTR], v11=s_xy[rb+XSTR+1], v12=s_xy[rb+XSTR+2];

    #pragma unroll
    for (int j = 0; j < 4; j++) {
        int rbn = rb + (j+2)*XSTR;
        __half2 v20=s_xy[rbn], v21=s_xy[rbn+1], v22=s_xy[rbn+2];

        __half2 gx2 = __hfma2(__hsub2(v12,v10), TWO2, __hadd2(__hsub2(v02,v00), __hsub2(v22,v20)));
        __half2 gy2 = __hfma2(__hsub2(v21,v01), TWO2, __hadd2(__hsub2(v20,v00), __hsub2(v22,v02)));
        __half2 lp2 = __hfma2(v11, NEG42, __hadd2(__hadd2(v01,v10), __hadd2(v12,v21)));

        float xi = __low2float(v11);
        float yp = __high2float(v11);

        int g = img + (oy + r0 + j)*IMW + (ox + c);
        float wv   = wt_g[g];
        float nprd = np_g[g];
        float nsyn = ns_g[g];

        p_rc += fabsf(yp*wv - xi*wv);

        bool body = (xi > 0.15f) & (xi < 0.85f);
        if (body) {
            p_nb += 1.f; p_sxi += xi; p_syp += yp;
            int b1 = min(max((int)(yp * (float)NBINS), 0), NBINS-1);
            atomicAdd(&s_hist[b1 >> 1], 1u << ((b1 & 1) * 16));
            int b2 = min(max((int)(xi * (float)NBINS), 0), NBINS-1);
            atomicAdd(&s_hist[NWORDS + (b2 >> 1)], 1u << ((b2 & 1) * 16));
        }

        // edge terms (packed half)
        pex = __hadd(pex, __habs(__hsub(__high2half(gx2), __low2half(gx2))));
        pey = __hadd(pey, __habs(__hsub(__high2half(gy2), __low2half(gy2))));

        // gradient magnitudes -> fp32 for thresholds
        __half2 gm2 = __hfma2(gx2, gx2, __hmul2(gy2, gy2));
        float gmi = sqrtf(__low2float(gm2)  + 1e-8f);
        float gmp = sqrtf(__high2float(gm2) + 1e-8f);

        bool tex = (gmi > 0.03f) & (gmi < 0.5f);
        if (tex) { p_ntex += 1.f; p_stex += fabsf(gmp - gmi); }

        bool flat = (gmi < 0.03f);
        if (flat) {
            p_nf += 1.f;
            __half2 la = __habs2(lp2);     // (|lap_i|, |lap_p|)
            phf = __hadd(phf, __habs(__hsub(__high2half(la), __hmul(c03, __low2half(la)))));
            p_ic += fmaxf(gmp - 2.0f*gmi, 0.f);
            if (body) {
                p_nfb += 1.f;
                plf = __hadd(plf, __habs(LU[j]));
                __half2 md = __habs2(__hsub2(G1P[j], LIP[j]));   // (|mid_i|, |mid_p|)
                pmid = __hadd(pmid, __habs(__hsub(__high2half(md), __hmul(c03, __low2half(md)))));
                p_syn += fabsf(nprd - nsyn);
            }
        }

        v00=v10; v01=v11; v02=v12; v10=v20; v11=v21; v12=v22;
    }

    // ---- block reduction of 15 partials ----
    float vals[NACC] = {p_rc, p_nb, p_sxi, p_syp,
                        __half2float(pex), __half2float(pey), p_ntex, p_stex,
                        p_nf, p_nfb, __half2float(plf), __half2float(pmid),
                        __half2float(phf), p_syn, p_ic};
    int lane = tid & 31, warp = tid >> 5;
    #pragma unroll
    for (int q = 0; q < NACC; q++) {
        float v = vals[q];
        #pragma unroll
        for (int o = 16; o > 0; o >>= 1) v += __shfl_down_sync(0xffffffffu, v, o);
        if (lane == 0) s_part[q][warp] = v;
    }
    __syncthreads();
    if (tid < NACC) {
        float s = 0.f;
        #pragma unroll
        for (int w = 0; w < 8; w++) s += s_part[tid][w];
        atomicAdd(&g_acc[tid], (double)s);
    }
    for (int i = tid; i < 2*NWORDS; i += NTHREADS) {
        unsigned int h = s_hist[i];
        if (h) atomicAdd(&g_histp[i], h);
    }

    // ---- last-block finalize ----
    __syncthreads();
    if (tid == 0) {
        __threadfence();
        unsigned t = atomicAdd(&g_ticket, 1u);
        s_last = (t == GRID_BLOCKS - 1);
    }
    __syncthreads();
    if (!s_last) return;
    __threadfence();

    unsigned int* s_cum = s_hist;
    const double nb = g_acc[1];

    for (int h = 0; h < 2; h++) {
        unsigned int w0 = g_histp[h*NWORDS + tid];
        unsigned int lo = w0 & 0xffffu, hi = w0 >> 16;
        unsigned int run = lo + hi;
        unsigned int v = run;
        #pragma unroll
        for (int o = 1; o < 32; o <<= 1) {
            unsigned int u = __shfl_up_sync(0xffffffffu, v, o);
            if (lane >= o) v += u;
        }
        __syncthreads();
        if (lane == 31) s_wtot[warp] = v;
        __syncthreads();
        unsigned int woff = 0;
        for (int w = 0; w < warp; w++) woff += s_wtot[w];
        unsigned int off = woff + v - run;
        s_cum[2*tid]   = off + lo;
        s_cum[2*tid+1] = off + run;
        __syncthreads();
        if (tid < 2) {
            double q = (tid == 0) ? 0.25 : 0.75;
            double pos = q * (nb - 1.0);
            int lo_i = 0, hi_i = NBINS - 1;
            while (lo_i < hi_i) {
                int m = (lo_i + hi_i) >> 1;
                if ((double)s_cum[m] > pos) hi_i = m; else lo_i = m + 1;
            }
            int b = lo_i;
            unsigned int cb = s_cum[b];
            unsigned int pv = b ? s_cum[b-1] : 0u;
            double cnt = (double)(cb - pv);
            double val = 0.0;
            if (cnt > 0.0) {
                double frac = (pos - (double)pv + 0.5) / cnt;
                frac = fmin(fmax(frac, 0.0), 1.0);
                val = ((double)b + frac) / (double)NBINS;
            }
            s_q[h*2 + tid] = val;
        }
        __syncthreads();
    }

    if (tid == 0) {
        const double n_all = (double)BATCH * IMH * IMW;
        double rc = g_acc[0] / n_all;
        double denb = fmax(nb, 1.0);
        double mean_in = g_acc[2] / denb;
        double mean_pr = g_acc[3] / denb;
        double dm  = mean_pr - mean_in;
        double d25 = s_q[0] - s_q[2];
        double d75 = s_q[1] - s_q[3];
        double hu  = dm*dm + 0.5*(d25*d25 + d75*d75);
        double loss_hu = (nb > 4096.0) ? hu : 0.0;
        double edge = g_acc[4]/n_all + g_acc[5]/n_all;
        double ntex = g_acc[6];
        double tex = (ntex > 100.0) ? g_acc[7]/fmax(ntex, 1.0) : 0.0;
        double nf = g_acc[8], nfb = g_acc[9];
        double lf  = (nfb > 100.0) ? g_acc[10]/fmax(nfb, 1.0) : 0.0;
        double mid = (nfb > 100.0) ? g_acc[11]/fmax(nfb, 1.0) : 0.0;
        double hf  = (nf  > 100.0) ? g_acc[12]/fmax(nf, 1.0)  : 0.0;
        double syn = (nfb > 100.0) ? g_acc[13]/fmax(nfb, 1.0) : 0.0;
        double ic  = (nf  > 100.0) ? g_acc[14]/fmax(nf, 1.0)  : 0.0;

        double total = 2.0*rc + 1.5*loss_hu + 1.0*edge + 0.8*tex
                     + 1.5*hf + 0.8*mid + 0.6*lf + 1.0*syn + 0.8*ic;
        out[0] = (float)total;
    }
    __syncthreads();

    for (int i = tid; i < 2*NWORDS; i += NTHREADS) g_histp[i] = 0u;
    if (tid < NACC) g_acc[tid] = 0.0;
    if (tid == 0) g_ticket = 0u;
}

extern "C" void kernel_launch(void* const* d_in, const int* in_sizes, int n_in,
                              void* d_out, int out_size) {
    const float* yp = (const float*)d_in[0];   // y_pred
    const float* np = (const float*)d_in[1];   // noise_pred
    const float* xi = (const float*)d_in[2];   // x_i
    // d_in[3] = x_ip1 (unused by reference)
    const float* xm = (const float*)d_in[4];   // x_mid
    const float* wt = (const float*)d_in[5];   // W
    const float* ns = (const float*)d_in[6];   // noise_synthetic
    float* out = (float*)d_out;

    cudaFuncSetAttribute(main_kernel,
                         cudaFuncAttributeMaxDynamicSharedMemorySize, SMEM_BYTES);

    dim3 grid(IMW / TILE, IMH / TILE, BATCH);
    main_kernel<<<grid, NTHREADS, SMEM_BYTES>>>(yp, np, xi, xm, wt, ns, out);
}